// round 9
// baseline (speedup 1.0000x reference)
#include <cuda_runtime.h>

namespace {
constexpr int BATCH = 1024;
constexpr int FEAT  = 1024;   // F (bias row handled in epilogue; weights have FEAT+1 rows)
constexpr int NCOLS = 256;    // per-op output columns
constexpr int NOUT  = 512;

constexpr int BM = 32;
constexpr int BN = 64;
constexpr int BK = 32;
constexpr int TM = 4;
constexpr int TN = 4;
constexpr int NTHR = 128;
constexpr int XSTRIDE = BM + 4;        // 36 floats -> 144B row stride, 16B aligned
constexpr int NSTAGE = FEAT / BK;      // 32
}

// Tropical GEMM:
//   dilated[b,n] = max_f ( x[b,f] + D[f,n] )        (out cols 256..511)
//   eroded [b,n] = min_f ( x[b,f] - E[f,n] )        (out cols 0..255)
// Erosion computed in the negated domain:  -eroded = max_f ( (-x[b,f]) + E[f,n] )
// so both halves share one fmaxf(acc, x + w) inner loop (uniform per-CTA branch
// only at load/store). Bias feature (x contribution = 0 in both domains)
// is a single epilogue fmaxf with W[FEAT, n].
__global__ __launch_bounds__(NTHR, 2)
void tropical_gemm(const float* __restrict__ x,
                   const float* __restrict__ dil,
                   const float* __restrict__ ero,
                   float* __restrict__ out)
{
    __shared__ __align__(16) float xs[2][BK][XSTRIDE];
    __shared__ __align__(16) float ws[2][BK][BN];

    const int tid = threadIdx.x;
    const int ct  = blockIdx.x;              // 0..7 : 0-3 erosion tiles, 4-7 dilation
    const bool is_ero = (ct < 4);
    const float sgn = is_ero ? -1.0f : 1.0f;
    const int n0 = (ct & 3) * BN;
    const float* __restrict__ w = is_ero ? ero : dil;
    const int m0 = blockIdx.y * BM;
    const int ocol0 = (is_ero ? 0 : NCOLS) + n0;

    const int tx = tid & 15;                 // output col group (tx*4)
    const int ty = tid >> 4;                 // output row group (ty*4)

    // x-tile loader: each thread loads 8 consecutive k of one row (transposed store)
    const int lxm = tid & 31;
    const int lxk = (tid >> 5) << 3;

    float acc[TM][TN];
#pragma unroll
    for (int i = 0; i < TM; ++i)
#pragma unroll
        for (int j = 0; j < TN; ++j)
            acc[i][j] = -__int_as_float(0x7f800000);   // -inf

    float4 xr0, xr1;
    float4 wr[4];
    const float* xrow = x + (m0 + lxm) * FEAT + lxk;

    // ---- prefetch + store stage 0 ----
    xr0 = *(const float4*)(xrow + 0);
    xr1 = *(const float4*)(xrow + 4);
#pragma unroll
    for (int j = 0; j < 4; ++j) {
        const int fid = tid + NTHR * j;
        const int kk = fid >> 4, c4 = fid & 15;
        wr[j] = *(const float4*)(w + kk * NCOLS + n0 + c4 * 4);
    }
    {
        const float xv0[4] = {xr0.x, xr0.y, xr0.z, xr0.w};
        const float xv1[4] = {xr1.x, xr1.y, xr1.z, xr1.w};
#pragma unroll
        for (int i = 0; i < 4; ++i) xs[0][lxk + i][lxm]     = sgn * xv0[i];
#pragma unroll
        for (int i = 0; i < 4; ++i) xs[0][lxk + 4 + i][lxm] = sgn * xv1[i];
#pragma unroll
        for (int j = 0; j < 4; ++j) {
            const int fid = tid + NTHR * j;
            const int kk = fid >> 4, c4 = fid & 15;
            *(float4*)&ws[0][kk][c4 * 4] = wr[j];
        }
    }
    __syncthreads();

    for (int s = 0; s < NSTAGE; ++s) {
        const int cur = s & 1;
        if (s + 1 < NSTAGE) {
            const int k0 = (s + 1) * BK;
            xr0 = *(const float4*)(xrow + k0);
            xr1 = *(const float4*)(xrow + k0 + 4);
#pragma unroll
            for (int j = 0; j < 4; ++j) {
                const int fid = tid + NTHR * j;
                const int kk = fid >> 4, c4 = fid & 15;
                wr[j] = *(const float4*)(w + (k0 + kk) * NCOLS + n0 + c4 * 4);
            }
        }
#pragma unroll 8
        for (int k = 0; k < BK; ++k) {
            const float4 xv = *(const float4*)&xs[cur][k][ty * 4];
            const float4 wv = *(const float4*)&ws[cur][k][tx * 4];
            const float xa[4] = {xv.x, xv.y, xv.z, xv.w};
            const float wa[4] = {wv.x, wv.y, wv.z, wv.w};
#pragma unroll
            for (int i = 0; i < TM; ++i)
#pragma unroll
                for (int j = 0; j < TN; ++j)
                    acc[i][j] = fmaxf(acc[i][j], xa[i] + wa[j]);
        }
        if (s + 1 < NSTAGE) {
            const int nxt = cur ^ 1;
            const float xv0[4] = {xr0.x, xr0.y, xr0.z, xr0.w};
            const float xv1[4] = {xr1.x, xr1.y, xr1.z, xr1.w};
#pragma unroll
            for (int i = 0; i < 4; ++i) xs[nxt][lxk + i][lxm]     = sgn * xv0[i];
#pragma unroll
            for (int i = 0; i < 4; ++i) xs[nxt][lxk + 4 + i][lxm] = sgn * xv1[i];
#pragma unroll
            for (int j = 0; j < 4; ++j) {
                const int fid = tid + NTHR * j;
                const int kk = fid >> 4, c4 = fid & 15;
                *(float4*)&ws[nxt][kk][c4 * 4] = wr[j];
            }
            __syncthreads();
        }
    }

    // ---- bias feature: k = FEAT, x contribution is 0 in both domains ----
    {
        const float4 wb = *(const float4*)(w + FEAT * NCOLS + n0 + tx * 4);
        const float wba[4] = {wb.x, wb.y, wb.z, wb.w};
#pragma unroll
        for (int i = 0; i < TM; ++i)
#pragma unroll
            for (int j = 0; j < TN; ++j)
                acc[i][j] = fmaxf(acc[i][j], wba[j]);
    }

    // ---- store (negate back for erosion) ----
#pragma unroll
    for (int i = 0; i < TM; ++i) {
        const int row = m0 + ty * 4 + i;
        float4 o;
        o.x = sgn * acc[i][0];
        o.y = sgn * acc[i][1];
        o.z = sgn * acc[i][2];
        o.w = sgn * acc[i][3];
        *(float4*)(out + row * NOUT + ocol0 + tx * 4) = o;
    }
}

extern "C" void kernel_launch(void* const* d_in, const int* in_sizes, int n_in,
                              void* d_out, int out_size) {
    const float* x   = (const float*)d_in[0];
    const float* dil = (const float*)d_in[1];
    const float* ero = (const float*)d_in[2];
    float* out = (float*)d_out;
    (void)in_sizes; (void)n_in; (void)out_size;

    dim3 grid(8, BATCH / BM);   // 8 col tiles (4 ero + 4 dil) x 32 row tiles = 256 CTAs
    tropical_gemm<<<grid, NTHR>>>(x, dil, ero, out);
}